// round 3
// baseline (speedup 1.0000x reference)
#include <cuda_runtime.h>
#include <math.h>
#include <stdint.h>

// Problem constants
#define BDIM   2
#define VDIM   162
#define SDIM   4096
#define VS     (VDIM * SDIM)        // 663552
#define ODIM   32
#define KCH    5
#define F1     16
#define F2     32
#define NROWS  648                  // 4 * 162 stacked (k, v) rows
#define NPAD   768                  // 6 n-tiles of 128
#define KPAD   192                  // u padded for B tile loads
#define MAXELEM ((size_t)BDIM * ODIM * VS)

typedef unsigned long long ULL;

// Scratch
__device__ float g_t1[BDIM * ODIM * VS];
__device__ float g_t2[BDIM * ODIM * VS];
__device__ float g_t3[BDIM * ODIM * VS];
__device__ float g_t4[BDIM * ODIM * VS];
__device__ float g_y [BDIM * ODIM * VS];
__device__ float g_sum[ODIM];
__device__ float g_sumsq[ODIM];
__device__ float g_scale[ODIM];
__device__ float g_shift[ODIM];
__device__ float g_Tm[4 * VDIM * VDIM];   // T1..T4, row-major [v_out][u]
__device__ float g_Tt[KPAD * NPAD];       // transposed/padded: [u][n], n=(k*162+v)

__device__ __forceinline__ const float* sel_cbuf(int sel, const float* ext) {
    switch (sel) {
        case 0: return g_t1; case 1: return g_t2; case 2: return g_t3;
        case 3: return g_t4; case 5: return ext; case 6: return g_y;
        default: return nullptr;
    }
}

// ---------------- f32x2 packed math helpers (sm_100 family feature) --------
__device__ __forceinline__ ULL f2pack(float lo, float hi) {
    ULL r; asm("mov.b64 %0, {%1, %2};" : "=l"(r) : "f"(lo), "f"(hi)); return r;
}
__device__ __forceinline__ void f2unpack(ULL v, float& lo, float& hi) {
    asm("mov.b64 {%0, %1}, %2;" : "=f"(lo), "=f"(hi) : "l"(v));
}
__device__ __forceinline__ ULL ffma2(ULL a, ULL b, ULL c) {
    ULL d; asm("fma.rn.f32x2 %0, %1, %2, %3;" : "=l"(d) : "l"(a), "l"(b), "l"(c));
    return d;
}

// ---------------- Chebyshev matrix precompute ------------------------------
__global__ void tmat_copy(const float* __restrict__ lap) {
    int i = blockIdx.x * blockDim.x + threadIdx.x;
    if (i < VDIM * VDIM) g_Tm[i] = lap[i];
}
// Tm[kdst] = 2 * lap * Tm[kdst-1] - (kdst==1 ? I : Tm[kdst-2])
__global__ void tmat_step(const float* __restrict__ lap, int kdst) {
    __shared__ float lrow[VDIM];
    int u = blockIdx.x, v = threadIdx.x;
    if (v < VDIM) lrow[v] = lap[u * VDIM + v];
    __syncthreads();
    if (v >= VDIM) return;
    const float* P = g_Tm + (kdst - 1) * VDIM * VDIM;
    float acc = 0.f;
    for (int w = 0; w < VDIM; w++) acc += lrow[w] * P[w * VDIM + v];
    float q = (kdst == 1) ? ((u == v) ? 1.f : 0.f)
                          : g_Tm[(kdst - 2) * VDIM * VDIM + u * VDIM + v];
    g_Tm[kdst * VDIM * VDIM + u * VDIM + v] = 2.f * acc - q;
}
// g_Tt[u][n] = T_k[v][u]  with n = k*162 + v; zero-pad u>=162 or n>=648
__global__ void pack_T() {
    int i = blockIdx.x * blockDim.x + threadIdx.x;
    if (i >= KPAD * NPAD) return;
    int u = i / NPAD, n = i % NPAD;
    float val = 0.f;
    if (u < VDIM && n < NROWS) {
        int k = (n >= 486) ? 3 : (n >= 324) ? 2 : (n >= 162) ? 1 : 0;
        int v = n - k * VDIM;
        val = g_Tm[k * VDIM * VDIM + v * VDIM + u];
    }
    g_Tt[i] = val;
}

// ---------------- Chebyshev GEMM (f32x2) -----------------------------------
// D[n, s] = sum_u Tt[u, n] * src[u, s]   per slice; n covers all 4 t_k.
// Block: 256 threads, tile 128(s) x 128(n), K chunk 32.
__global__ __launch_bounds__(256) void cheb_gemm(
    const float* __restrict__ ext, int srcSel, int useBn)
{
    __shared__ float As[32][128];   // [kk][s]
    __shared__ ULL   Bp[32][128];   // [kk][n]  packed (b, b)

    const int tid = threadIdx.x;
    const int tx = tid & 15;        // s dir
    const int ty = tid >> 4;        // n dir (16)
    const int s0 = blockIdx.x * 128;
    const int n0 = blockIdx.y * 128;
    const int slice = blockIdx.z;

    const float* src = sel_cbuf(srcSel, ext) + (size_t)slice * VS;
    float sc = 1.f, sh = 0.f;
    if (useBn) { int ch = slice & (ODIM - 1); sc = g_scale[ch]; sh = g_shift[ch]; }

    ULL acc[8][4];
#pragma unroll
    for (int i = 0; i < 8; i++)
#pragma unroll
        for (int j = 0; j < 4; j++) acc[i][j] = 0ull;

    for (int k0 = 0; k0 < VDIM; k0 += 32) {
        // Fill As (with optional BN+ReLU on the fly)
#pragma unroll
        for (int t = 0; t < 4; t++) {
            int i = tid + t * 256;          // 1024 float4
            int kk = i >> 5, s4 = i & 31;
            float4 v = make_float4(0.f, 0.f, 0.f, 0.f);
            if (k0 + kk < VDIM)
                v = *(const float4*)&src[(size_t)(k0 + kk) * SDIM + s0 + s4 * 4];
            if (useBn) {
                v.x = fmaxf(fmaf(v.x, sc, sh), 0.f);
                v.y = fmaxf(fmaf(v.y, sc, sh), 0.f);
                v.z = fmaxf(fmaf(v.z, sc, sh), 0.f);
                v.w = fmaxf(fmaf(v.w, sc, sh), 0.f);
            }
            *(float4*)&As[kk][s4 * 4] = v;
        }
        // Fill Bp packed duplicates
#pragma unroll
        for (int t = 0; t < 4; t++) {
            int i = tid + t * 256;
            int kk = i >> 5, n4 = i & 31;
            float4 v = *(const float4*)&g_Tt[(size_t)(k0 + kk) * NPAD + n0 + n4 * 4];
            Bp[kk][n4 * 4 + 0] = f2pack(v.x, v.x);
            Bp[kk][n4 * 4 + 1] = f2pack(v.y, v.y);
            Bp[kk][n4 * 4 + 2] = f2pack(v.z, v.z);
            Bp[kk][n4 * 4 + 3] = f2pack(v.w, v.w);
        }
        __syncthreads();

#pragma unroll
        for (int kk = 0; kk < 32; kk++) {
            ulonglong2 aLo = *(const ulonglong2*)&As[kk][tx * 4];
            ulonglong2 aHi = *(const ulonglong2*)&As[kk][64 + tx * 4];
            ulonglong2 b01 = *(const ulonglong2*)&Bp[kk][ty * 4];
            ulonglong2 b23 = *(const ulonglong2*)&Bp[kk][ty * 4 + 2];
            ulonglong2 b45 = *(const ulonglong2*)&Bp[kk][64 + ty * 4];
            ulonglong2 b67 = *(const ulonglong2*)&Bp[kk][64 + ty * 4 + 2];
            ULL ap[4] = {aLo.x, aLo.y, aHi.x, aHi.y};
            ULL bv[8] = {b01.x, b01.y, b23.x, b23.y, b45.x, b45.y, b67.x, b67.y};
#pragma unroll
            for (int i = 0; i < 8; i++)
#pragma unroll
                for (int j = 0; j < 4; j++)
                    acc[i][j] = ffma2(ap[j], bv[i], acc[i][j]);
        }
        __syncthreads();
    }

    // Epilogue: scatter rows to t1..t4
    float* tk[4] = {g_t1, g_t2, g_t3, g_t4};
#pragma unroll
    for (int i = 0; i < 8; i++) {
        int n = n0 + ((i < 4) ? (ty * 4 + i) : (64 + ty * 4 + i - 4));
        if (n >= NROWS) continue;
        int k = (n >= 486) ? 3 : (n >= 324) ? 2 : (n >= 162) ? 1 : 0;
        int v = n - k * VDIM;
        float* dst = tk[k] + (size_t)slice * VS + (size_t)v * SDIM + s0;
        float f0, f1, f2, f3;
        f2unpack(acc[i][0], f0, f1); f2unpack(acc[i][1], f2, f3);
        *(float4*)&dst[tx * 4] = make_float4(f0, f1, f2, f3);
        f2unpack(acc[i][2], f0, f1); f2unpack(acc[i][3], f2, f3);
        *(float4*)&dst[64 + tx * 4] = make_float4(f0, f1, f2, f3);
    }
}

// ---------------- combine (f32x2) + fused BN stats -------------------------
// y[b,o,:,n] = bias[o] + sum_{k,f} w[k,f,o] * t_k[b,f,:,n]
__global__ __launch_bounds__(128) void combine(
    const float* __restrict__ x0ext, int x0Sel, int Fin, int useBn,
    const float* __restrict__ w, const float* __restrict__ bias)
{
    const int KF = KCH * Fin;
    __shared__ float Ws[KCH * F2][32];
    __shared__ float Ts[16][256];
    __shared__ const float* rows[KCH * F2];
    __shared__ float s_sum[ODIM], s_sq[ODIM];
    __shared__ float s_sc[F2], s_sh[F2];

    const int tid = threadIdx.x;
    const int b   = blockIdx.y;
    const size_t n0 = (size_t)blockIdx.x * 256;

    const float* x0 = sel_cbuf(x0Sel, x0ext);
    const float* bufs[KCH] = {x0, g_t1, g_t2, g_t3, g_t4};

    for (int i = tid; i < KF; i += 128) {
        int k = i / Fin, f = i % Fin;
        rows[i] = bufs[k] + ((size_t)(b * Fin + f)) * VS;
    }
    for (int i = tid; i < KF * 32; i += 128) Ws[0][i] = w[i];
    if (tid < ODIM) { s_sum[tid] = 0.f; s_sq[tid] = 0.f; }
    if (tid < Fin) {
        s_sc[tid] = useBn ? g_scale[tid] : 1.f;
        s_sh[tid] = useBn ? g_shift[tid] : 0.f;
    }
    __syncthreads();

    const int to = tid & 3;    // o dir (4)
    const int tn = tid >> 2;   // n dir (32)

    ULL acc[8][4];
#pragma unroll
    for (int i = 0; i < 8; i++)
#pragma unroll
        for (int j = 0; j < 4; j++) acc[i][j] = 0ull;

    for (int kc0 = 0; kc0 < KF; kc0 += 16) {
        for (int i = tid; i < 16 * 64; i += 128) {
            int kk = i >> 6, jq = i & 63;
            int kr = kc0 + kk;
            float4 v = *(const float4*)&rows[kr][n0 + jq * 4];
            if (useBn && kr < Fin) {        // t0 rows = raw y -> relu(bn(y))
                float a = s_sc[kr], c = s_sh[kr];
                v.x = fmaxf(fmaf(v.x, a, c), 0.f);
                v.y = fmaxf(fmaf(v.y, a, c), 0.f);
                v.z = fmaxf(fmaf(v.z, a, c), 0.f);
                v.w = fmaxf(fmaf(v.w, a, c), 0.f);
            }
            *(float4*)&Ts[kk][jq * 4] = v;
        }
        __syncthreads();
#pragma unroll 4
        for (int kk = 0; kk < 16; kk++) {
            float a[8];
            *(float4*)&a[0] = *(const float4*)&Ws[kc0 + kk][to * 4];
            *(float4*)&a[4] = *(const float4*)&Ws[kc0 + kk][16 + to * 4];
            ulonglong2 t01 = *(const ulonglong2*)&Ts[kk][tn * 4];
            ulonglong2 t23 = *(const ulonglong2*)&Ts[kk][128 + tn * 4];
            ULL bv[4] = {t01.x, t01.y, t23.x, t23.y};
#pragma unroll
            for (int i = 0; i < 8; i++) {
                ULL ad = f2pack(a[i], a[i]);
#pragma unroll
                for (int j = 0; j < 4; j++)
                    acc[i][j] = ffma2(ad, bv[j], acc[i][j]);
            }
        }
        __syncthreads();
    }

#pragma unroll
    for (int i = 0; i < 8; i++) {
        int o = (i < 4) ? (to * 4 + i) : (16 + to * 4 + i - 4);
        float bo = bias[o];
        float* yo = g_y + ((size_t)(b * ODIM + o)) * VS + n0;
        float f0, f1, f2, f3;
        f2unpack(acc[i][0], f0, f1); f2unpack(acc[i][1], f2, f3);
        float4 v0 = make_float4(f0 + bo, f1 + bo, f2 + bo, f3 + bo);
        f2unpack(acc[i][2], f0, f1); f2unpack(acc[i][3], f2, f3);
        float4 v1 = make_float4(f0 + bo, f1 + bo, f2 + bo, f3 + bo);
        *(float4*)&yo[tn * 4]       = v0;
        *(float4*)&yo[128 + tn * 4] = v1;
        float ps = v0.x + v0.y + v0.z + v0.w + v1.x + v1.y + v1.z + v1.w;
        float pq = v0.x*v0.x + v0.y*v0.y + v0.z*v0.z + v0.w*v0.w
                 + v1.x*v1.x + v1.y*v1.y + v1.z*v1.z + v1.w*v1.w;
        atomicAdd(&s_sum[o], ps);
        atomicAdd(&s_sq[o],  pq);
    }
    __syncthreads();
    if (tid < ODIM) {
        atomicAdd(&g_sum[tid],   s_sum[tid]);
        atomicAdd(&g_sumsq[tid], s_sq[tid]);
    }
}

__global__ void zero_stats() {
    int i = threadIdx.x;
    if (i < ODIM) { g_sum[i] = 0.f; g_sumsq[i] = 0.f; }
}

__global__ void finalize_stats(const float* __restrict__ gamma,
                               const float* __restrict__ beta, float ncnt)
{
    int o = threadIdx.x;
    if (o < ODIM) {
        float mean = g_sum[o] / ncnt;
        float var  = g_sumsq[o] / ncnt - mean * mean;
        float sc   = gamma[o] * rsqrtf(var + 1e-5f);
        g_scale[o] = sc;
        g_shift[o] = beta[o] - mean * sc;
    }
}

// Final layer-2 BN+ReLU -> d_out
__global__ void norm_relu(float* __restrict__ out)
{
    const size_t total4 = MAXELEM / 4;
    const size_t stride = (size_t)gridDim.x * blockDim.x;
    for (size_t i = (size_t)blockIdx.x * blockDim.x + threadIdx.x;
         i < total4; i += stride) {
        size_t e = i * 4;
        int o = (int)((e / VS) % ODIM);
        float sc = g_scale[o], sh = g_shift[o];
        float4 v = ((const float4*)g_y)[i];
        v.x = fmaxf(fmaf(v.x, sc, sh), 0.f);
        v.y = fmaxf(fmaf(v.y, sc, sh), 0.f);
        v.z = fmaxf(fmaf(v.z, sc, sh), 0.f);
        v.w = fmaxf(fmaf(v.w, sc, sh), 0.f);
        ((float4*)out)[i] = v;
    }
}

// ---------------------------------------------------------------------------
extern "C" void kernel_launch(void* const* d_in, const int* in_sizes, int n_in,
                              void* d_out, int out_size)
{
    const float* x   = (const float*)d_in[0];
    const float* lap = (const float*)d_in[1];
    const float* w1  = (const float*)d_in[2];
    const float* b1  = (const float*)d_in[3];
    const float* g1  = (const float*)d_in[4];
    const float* be1 = (const float*)d_in[5];
    const float* w2  = (const float*)d_in[6];
    const float* b2  = (const float*)d_in[7];
    const float* g2  = (const float*)d_in[8];
    const float* be2 = (const float*)d_in[9];
    float* out = (float*)d_out;
    (void)in_sizes; (void)n_in; (void)out_size;

    const float ncnt = (float)((size_t)BDIM * VS);
    dim3 gcomb(VS / 256, BDIM);

    // Precompute T1..T4 and transposed/padded operand
    tmat_copy<<<(VDIM * VDIM + 255) / 256, 256>>>(lap);
    tmat_step<<<VDIM, 192>>>(lap, 1);
    tmat_step<<<VDIM, 192>>>(lap, 2);
    tmat_step<<<VDIM, 192>>>(lap, 3);
    pack_T<<<(KPAD * NPAD + 255) / 256, 256>>>();

    // ---- Layer 1 ----
    cheb_gemm<<<dim3(SDIM / 128, NPAD / 128, BDIM * F1), 256>>>(x, 5, 0);
    zero_stats<<<1, 32>>>();
    combine<<<gcomb, 128>>>(x, 5, F1, 0, w1, b1);
    finalize_stats<<<1, 32>>>(g1, be1, ncnt);
    // (layer-1 BN+ReLU fused into layer-2 consumers)

    // ---- Layer 2 ----
    cheb_gemm<<<dim3(SDIM / 128, NPAD / 128, BDIM * F2), 256>>>(nullptr, 6, 1);
    zero_stats<<<1, 32>>>();
    combine<<<gcomb, 128>>>(nullptr, 6, F2, 1, w2, b2);
    finalize_stats<<<1, 32>>>(g2, be2, ncnt);
    norm_relu<<<2048, 256>>>(out);
}

// round 4
// speedup vs baseline: 1.3236x; 1.3236x over previous
#include <cuda_runtime.h>
#include <math.h>
#include <stdint.h>

// Problem constants
#define BDIM   2
#define VDIM   162
#define SDIM   4096
#define VS     (VDIM * SDIM)        // 663552
#define ODIM   32
#define KCH    5
#define F1     16
#define F2     32
#define NROWS  648                  // 4 * 162 stacked (k, v) rows
#define NPAD   704                  // 11 n-tiles of 64
#define MAXELEM ((size_t)BDIM * ODIM * VS)

typedef unsigned long long ULL;

// Scratch
__device__ float g_t1[BDIM * ODIM * VS];
__device__ float g_t2[BDIM * ODIM * VS];
__device__ float g_t3[BDIM * ODIM * VS];
__device__ float g_t4[BDIM * ODIM * VS];
__device__ float g_y [BDIM * ODIM * VS];
__device__ float g_sum[ODIM];
__device__ float g_sumsq[ODIM];
__device__ float g_scale[ODIM];
__device__ float g_shift[ODIM];
__device__ float g_Tm[4 * VDIM * VDIM];   // T1..T4, row-major [v_out][u]
__device__ float g_Tt[VDIM * NPAD];       // transposed/padded: [u][n], n=k*162+v

__device__ __forceinline__ const float* sel_cbuf(int sel, const float* ext) {
    switch (sel) {
        case 0: return g_t1; case 1: return g_t2; case 2: return g_t3;
        case 3: return g_t4; case 5: return ext; case 6: return g_y;
        default: return nullptr;
    }
}

// ---------------- f32x2 packed helpers -------------------------------------
__device__ __forceinline__ ULL f2dup(float b) {
    ULL r; asm("mov.b64 %0, {%1, %1};" : "=l"(r) : "f"(b)); return r;
}
__device__ __forceinline__ void f2unpack(ULL v, float& lo, float& hi) {
    asm("mov.b64 {%0, %1}, %2;" : "=f"(lo), "=f"(hi) : "l"(v));
}
__device__ __forceinline__ ULL ffma2(ULL a, ULL b, ULL c) {
    ULL d; asm("fma.rn.f32x2 %0, %1, %2, %3;" : "=l"(d) : "l"(a), "l"(b), "l"(c));
    return d;
}

// ---------------- Chebyshev matrix precompute ------------------------------
__global__ void tmat_copy(const float* __restrict__ lap) {
    int i = blockIdx.x * blockDim.x + threadIdx.x;
    if (i < VDIM * VDIM) g_Tm[i] = lap[i];
}
__global__ void tmat_step(const float* __restrict__ lap, int kdst) {
    __shared__ float lrow[VDIM];
    int u = blockIdx.x, v = threadIdx.x;
    if (v < VDIM) lrow[v] = lap[u * VDIM + v];
    __syncthreads();
    if (v >= VDIM) return;
    const float* P = g_Tm + (kdst - 1) * VDIM * VDIM;
    float acc = 0.f;
    for (int w = 0; w < VDIM; w++) acc += lrow[w] * P[w * VDIM + v];
    float q = (kdst == 1) ? ((u == v) ? 1.f : 0.f)
                          : g_Tm[(kdst - 2) * VDIM * VDIM + u * VDIM + v];
    g_Tm[kdst * VDIM * VDIM + u * VDIM + v] = 2.f * acc - q;
}
// g_Tt[u][n] = T_k[v][u], n = k*162+v; zero-pad n >= 648
__global__ void pack_T() {
    int i = blockIdx.x * blockDim.x + threadIdx.x;
    if (i >= VDIM * NPAD) return;
    int u = i / NPAD, n = i % NPAD;
    float val = 0.f;
    if (n < NROWS) {
        int k = (n >= 486) ? 3 : (n >= 324) ? 2 : (n >= 162) ? 1 : 0;
        int v = n - k * VDIM;
        val = g_Tm[k * VDIM * VDIM + v * VDIM + u];
    }
    g_Tt[i] = val;
}

// ---------------- Flattened Chebyshev GEMM (FFMA2) -------------------------
// D[n, s] = sum_u Tt[u, n] * src[u, s] per slice; n covers all t1..t4 rows.
// Block 128 thr, tile 128(s) x 64(n), per-thread 8x8, K = 162 in 3 x 54.
__global__ __launch_bounds__(128) void cheb_gemm(
    const float* __restrict__ ext, int srcSel, int useBn)
{
    __shared__ float As[54][128];
    __shared__ float Bs[54][64];

    const int tid = threadIdx.x;
    const int tx = tid & 15;        // s dir (16)
    const int ty = tid >> 4;        // n dir (8)
    const int n0 = blockIdx.x * 64;
    const int s0 = blockIdx.y * 128;
    const int slice = blockIdx.z;

    const float* src = sel_cbuf(srcSel, ext) + (size_t)slice * VS;
    float sc = 1.f, sh = 0.f;
    if (useBn) { int ch = slice & (ODIM - 1); sc = g_scale[ch]; sh = g_shift[ch]; }

    ULL acc[8][4];
#pragma unroll
    for (int i = 0; i < 8; i++)
#pragma unroll
        for (int j = 0; j < 4; j++) acc[i][j] = 0ull;

    for (int k0 = 0; k0 < VDIM; k0 += 54) {
        // A tile: As[kk][s] (with layer-1 BN+ReLU fused on load for layer 2)
        for (int i = tid; i < 54 * 32; i += 128) {
            int kk = i >> 5, s4 = i & 31;
            float4 v = *(const float4*)&src[(size_t)(k0 + kk) * SDIM + s0 + s4 * 4];
            if (useBn) {
                v.x = fmaxf(fmaf(v.x, sc, sh), 0.f);
                v.y = fmaxf(fmaf(v.y, sc, sh), 0.f);
                v.z = fmaxf(fmaf(v.z, sc, sh), 0.f);
                v.w = fmaxf(fmaf(v.w, sc, sh), 0.f);
            }
            *(float4*)&As[kk][s4 * 4] = v;
        }
        // B tile: Bs[kk][n] (plain floats; NPAD covers n0+64)
        for (int i = tid; i < 54 * 16; i += 128) {
            int kk = i >> 4, n4 = i & 15;
            *(float4*)&Bs[kk][n4 * 4] =
                *(const float4*)&g_Tt[(size_t)(k0 + kk) * NPAD + n0 + n4 * 4];
        }
        __syncthreads();

#pragma unroll 2
        for (int kk = 0; kk < 54; kk++) {
            ulonglong2 a01 = *(const ulonglong2*)&As[kk][tx * 4];
            ulonglong2 a23 = *(const ulonglong2*)&As[kk][64 + tx * 4];
            float4 bl = *(const float4*)&Bs[kk][ty * 4];
            float4 bh = *(const float4*)&Bs[kk][32 + ty * 4];
            ULL ap[4] = {a01.x, a01.y, a23.x, a23.y};
            ULL bd[8] = {f2dup(bl.x), f2dup(bl.y), f2dup(bl.z), f2dup(bl.w),
                         f2dup(bh.x), f2dup(bh.y), f2dup(bh.z), f2dup(bh.w)};
#pragma unroll
            for (int i = 0; i < 8; i++)
#pragma unroll
                for (int j = 0; j < 4; j++)
                    acc[i][j] = ffma2(ap[j], bd[i], acc[i][j]);
        }
        __syncthreads();
    }

    // Epilogue: scatter rows to t1..t4
    float* tk[4] = {g_t1, g_t2, g_t3, g_t4};
#pragma unroll
    for (int i = 0; i < 8; i++) {
        int n = n0 + ((i < 4) ? (ty * 4 + i) : (32 + ty * 4 + i - 4));
        if (n >= NROWS) continue;
        int k = (n >= 486) ? 3 : (n >= 324) ? 2 : (n >= 162) ? 1 : 0;
        int v = n - k * VDIM;
        float* dst = tk[k] + (size_t)slice * VS + (size_t)v * SDIM + s0;
        float f0, f1, f2, f3;
        f2unpack(acc[i][0], f0, f1); f2unpack(acc[i][1], f2, f3);
        *(float4*)&dst[tx * 4] = make_float4(f0, f1, f2, f3);
        f2unpack(acc[i][2], f0, f1); f2unpack(acc[i][3], f2, f3);
        *(float4*)&dst[64 + tx * 4] = make_float4(f0, f1, f2, f3);
    }
}

// ---------------- combine (scalar, R1-proven) + fused BN stats -------------
__global__ __launch_bounds__(128) void combine(
    const float* __restrict__ x0ext, int x0Sel, int Fin, int useBn,
    const float* __restrict__ w, const float* __restrict__ bias)
{
    const int KF = KCH * Fin;
    __shared__ float Ws[KCH * F2][32];
    __shared__ float Ts[16][256];
    __shared__ const float* rows[KCH * F2];
    __shared__ float s_sum[ODIM], s_sq[ODIM];
    __shared__ float s_sc[F2], s_sh[F2];

    const int tid = threadIdx.x;
    const int b   = blockIdx.y;
    const size_t n0 = (size_t)blockIdx.x * 256;

    const float* x0 = sel_cbuf(x0Sel, x0ext);
    const float* bufs[KCH] = {x0, g_t1, g_t2, g_t3, g_t4};

    for (int i = tid; i < KF; i += 128) {
        int k = i / Fin, f = i % Fin;
        rows[i] = bufs[k] + ((size_t)(b * Fin + f)) * VS;
    }
    for (int i = tid; i < KF * 32; i += 128) Ws[0][i] = w[i];
    if (tid < ODIM) { s_sum[tid] = 0.f; s_sq[tid] = 0.f; }
    if (tid < Fin) {
        s_sc[tid] = useBn ? g_scale[tid] : 1.f;
        s_sh[tid] = useBn ? g_shift[tid] : 0.f;
    }
    __syncthreads();

    const int to = tid & 3;    // o dir (4)
    const int tn = tid >> 2;   // n dir (32)

    float acc[8][8];
#pragma unroll
    for (int i = 0; i < 8; i++)
#pragma unroll
        for (int j = 0; j < 8; j++) acc[i][j] = 0.f;

    for (int kc0 = 0; kc0 < KF; kc0 += 16) {
        for (int i = tid; i < 16 * 64; i += 128) {
            int kk = i >> 6, jq = i & 63;
            int kr = kc0 + kk;
            float4 v = *(const float4*)&rows[kr][n0 + jq * 4];
            if (useBn && kr < Fin) {        // t0 rows = raw y -> relu(bn(y))
                float a = s_sc[kr], c = s_sh[kr];
                v.x = fmaxf(fmaf(v.x, a, c), 0.f);
                v.y = fmaxf(fmaf(v.y, a, c), 0.f);
                v.z = fmaxf(fmaf(v.z, a, c), 0.f);
                v.w = fmaxf(fmaf(v.w, a, c), 0.f);
            }
            *(float4*)&Ts[kk][jq * 4] = v;
        }
        __syncthreads();
#pragma unroll 2
        for (int kk = 0; kk < 16; kk++) {
            float a[8], bb[8];
            *(float4*)&a[0]  = *(const float4*)&Ws[kc0 + kk][to * 4];
            *(float4*)&a[4]  = *(const float4*)&Ws[kc0 + kk][16 + to * 4];
            *(float4*)&bb[0] = *(const float4*)&Ts[kk][tn * 4];
            *(float4*)&bb[4] = *(const float4*)&Ts[kk][128 + tn * 4];
#pragma unroll
            for (int i = 0; i < 8; i++)
#pragma unroll
                for (int j = 0; j < 8; j++)
                    acc[i][j] += a[i] * bb[j];
        }
        __syncthreads();
    }

#pragma unroll
    for (int i = 0; i < 8; i++) {
        int o = (i < 4) ? (to * 4 + i) : (16 + to * 4 + i - 4);
        float bo = bias[o];
        float* yo = g_y + ((size_t)(b * ODIM + o)) * VS + n0;
        float4 v0, v1;
        v0.x = acc[i][0] + bo; v0.y = acc[i][1] + bo;
        v0.z = acc[i][2] + bo; v0.w = acc[i][3] + bo;
        v1.x = acc[i][4] + bo; v1.y = acc[i][5] + bo;
        v1.z = acc[i][6] + bo; v1.w = acc[i][7] + bo;
        *(float4*)&yo[tn * 4]       = v0;
        *(float4*)&yo[128 + tn * 4] = v1;
        float ps = v0.x + v0.y + v0.z + v0.w + v1.x + v1.y + v1.z + v1.w;
        float pq = v0.x*v0.x + v0.y*v0.y + v0.z*v0.z + v0.w*v0.w
                 + v1.x*v1.x + v1.y*v1.y + v1.z*v1.z + v1.w*v1.w;
        atomicAdd(&s_sum[o], ps);
        atomicAdd(&s_sq[o],  pq);
    }
    __syncthreads();
    if (tid < ODIM) {
        atomicAdd(&g_sum[tid],   s_sum[tid]);
        atomicAdd(&g_sumsq[tid], s_sq[tid]);
    }
}

__global__ void zero_stats() {
    int i = threadIdx.x;
    if (i < ODIM) { g_sum[i] = 0.f; g_sumsq[i] = 0.f; }
}

__global__ void finalize_stats(const float* __restrict__ gamma,
                               const float* __restrict__ beta, float ncnt)
{
    int o = threadIdx.x;
    if (o < ODIM) {
        float mean = g_sum[o] / ncnt;
        float var  = g_sumsq[o] / ncnt - mean * mean;
        float sc   = gamma[o] * rsqrtf(var + 1e-5f);
        g_scale[o] = sc;
        g_shift[o] = beta[o] - mean * sc;
    }
}

// Final layer-2 BN+ReLU -> d_out
__global__ void norm_relu(float* __restrict__ out)
{
    const size_t total4 = MAXELEM / 4;
    const size_t stride = (size_t)gridDim.x * blockDim.x;
    for (size_t i = (size_t)blockIdx.x * blockDim.x + threadIdx.x;
         i < total4; i += stride) {
        size_t e = i * 4;
        int o = (int)((e / VS) % ODIM);
        float sc = g_scale[o], sh = g_shift[o];
        float4 v = ((const float4*)g_y)[i];
        v.x = fmaxf(fmaf(v.x, sc, sh), 0.f);
        v.y = fmaxf(fmaf(v.y, sc, sh), 0.f);
        v.z = fmaxf(fmaf(v.z, sc, sh), 0.f);
        v.w = fmaxf(fmaf(v.w, sc, sh), 0.f);
        ((float4*)out)[i] = v;
    }
}

// ---------------------------------------------------------------------------
extern "C" void kernel_launch(void* const* d_in, const int* in_sizes, int n_in,
                              void* d_out, int out_size)
{
    const float* x   = (const float*)d_in[0];
    const float* lap = (const float*)d_in[1];
    const float* w1  = (const float*)d_in[2];
    const float* b1  = (const float*)d_in[3];
    const float* g1  = (const float*)d_in[4];
    const float* be1 = (const float*)d_in[5];
    const float* w2  = (const float*)d_in[6];
    const float* b2  = (const float*)d_in[7];
    const float* g2  = (const float*)d_in[8];
    const float* be2 = (const float*)d_in[9];
    float* out = (float*)d_out;
    (void)in_sizes; (void)n_in; (void)out_size;

    const float ncnt = (float)((size_t)BDIM * VS);
    dim3 gcomb(VS / 256, BDIM);

    // Precompute T1..T4 and transposed/padded operand
    tmat_copy<<<(VDIM * VDIM + 255) / 256, 256>>>(lap);
    tmat_step<<<VDIM, 192>>>(lap, 1);
    tmat_step<<<VDIM, 192>>>(lap, 2);
    tmat_step<<<VDIM, 192>>>(lap, 3);
    pack_T<<<(VDIM * NPAD + 255) / 256, 256>>>();

    // ---- Layer 1 ----
    cheb_gemm<<<dim3(NPAD / 64, SDIM / 128, BDIM * F1), 128>>>(x, 5, 0);
    zero_stats<<<1, 32>>>();
    combine<<<gcomb, 128>>>(x, 5, F1, 0, w1, b1);
    finalize_stats<<<1, 32>>>(g1, be1, ncnt);
    // (layer-1 BN+ReLU fused into layer-2 consumers)

    // ---- Layer 2 ----
    cheb_gemm<<<dim3(NPAD / 64, SDIM / 128, BDIM * F2), 128>>>(nullptr, 6, 1);
    zero_stats<<<1, 32>>>();
    combine<<<gcomb, 128>>>(nullptr, 6, F2, 1, w2, b2);
    finalize_stats<<<1, 32>>>(g2, be2, ncnt);
    norm_relu<<<2048, 256>>>(out);
}

// round 5
// speedup vs baseline: 2.0433x; 1.5437x over previous
#include <cuda_runtime.h>
#include <cuda_bf16.h>
#include <math.h>
#include <stdint.h>

// Problem constants
#define BDIM   2
#define VDIM   162
#define SDIM   4096
#define VS     (VDIM * SDIM)        // 663552
#define ODIM   32
#define KCH    5
#define F1     16
#define F2     32
#define NROWS  648                  // 4 * 162 stacked (k, v) rows
#define NPAD2  768                  // 6 m-tiles of 128
#define KPAD2  176                  // 11 k-chunks of 16
#define NKC    11
#define MAXELEM ((size_t)BDIM * ODIM * VS)

typedef unsigned long long ULL;

// Scratch
__device__ float g_t1[BDIM * ODIM * VS];
__device__ float g_t2[BDIM * ODIM * VS];
__device__ float g_t3[BDIM * ODIM * VS];
__device__ float g_t4[BDIM * ODIM * VS];
__device__ float g_y [BDIM * ODIM * VS];
__device__ float g_sum[ODIM];
__device__ float g_sumsq[ODIM];
__device__ float g_scale[ODIM];
__device__ float g_shift[ODIM];
__device__ float g_Tm[4 * VDIM * VDIM];                        // T1..T4 [v][u]
__device__ __align__(16) __nv_bfloat16 g_Thi[NPAD2 * KPAD2];   // A hi [m][k]
__device__ __align__(16) __nv_bfloat16 g_Tlo[NPAD2 * KPAD2];   // A lo
__device__ __align__(16) __nv_bfloat16 g_bhi[(size_t)BDIM * F2 * KPAD2 * SDIM];
__device__ __align__(16) __nv_bfloat16 g_blo[(size_t)BDIM * F2 * KPAD2 * SDIM];

__device__ __forceinline__ const float* sel_cbuf(int sel, const float* ext) {
    switch (sel) {
        case 0: return g_t1; case 1: return g_t2; case 2: return g_t3;
        case 3: return g_t4; case 5: return ext; case 6: return g_y;
        default: return nullptr;
    }
}

// ---------------- packed helpers -------------------------------------------
__device__ __forceinline__ ULL f2dup(float b) {
    ULL r; asm("mov.b64 %0, {%1, %1};" : "=l"(r) : "f"(b)); return r;
}
__device__ __forceinline__ void f2unpack(ULL v, float& lo, float& hi) {
    asm("mov.b64 {%0, %1}, %2;" : "=f"(lo), "=f"(hi) : "l"(v));
}
__device__ __forceinline__ ULL ffma2(ULL a, ULL b, ULL c) {
    ULL d; asm("fma.rn.f32x2 %0, %1, %2, %3;" : "=l"(d) : "l"(a), "l"(b), "l"(c));
    return d;
}
__device__ __forceinline__ uint32_t smem_u32(const void* p) {
    uint32_t a;
    asm("{ .reg .u64 t; cvta.to.shared.u64 t, %1; cvt.u32.u64 %0, t; }" : "=r"(a) : "l"(p));
    return a;
}
__device__ __forceinline__ void cpa16(uint32_t s, const void* g) {
    asm volatile("cp.async.cg.shared.global [%0], [%1], 16;" :: "r"(s), "l"(g));
}
#define CP_COMMIT() asm volatile("cp.async.commit_group;" ::: "memory")
#define CP_WAIT(n)  asm volatile("cp.async.wait_group %0;" :: "n"(n) : "memory")

__device__ __forceinline__ void ldsm_x4(uint32_t* r, uint32_t a) {
    asm volatile("ldmatrix.sync.aligned.m8n8.x4.shared.b16 {%0,%1,%2,%3}, [%4];"
        : "=r"(r[0]), "=r"(r[1]), "=r"(r[2]), "=r"(r[3]) : "r"(a));
}
__device__ __forceinline__ void ldsm_x4t(uint32_t* r, uint32_t a) {
    asm volatile("ldmatrix.sync.aligned.m8n8.x4.trans.shared.b16 {%0,%1,%2,%3}, [%4];"
        : "=r"(r[0]), "=r"(r[1]), "=r"(r[2]), "=r"(r[3]) : "r"(a));
}
__device__ __forceinline__ void mma_bf16(float* c, const uint32_t* a, const uint32_t* b) {
    asm volatile("mma.sync.aligned.m16n8k16.row.col.f32.bf16.bf16.f32 "
        "{%0,%1,%2,%3}, {%4,%5,%6,%7}, {%8,%9}, {%0,%1,%2,%3};"
        : "+f"(c[0]), "+f"(c[1]), "+f"(c[2]), "+f"(c[3])
        : "r"(a[0]), "r"(a[1]), "r"(a[2]), "r"(a[3]), "r"(b[0]), "r"(b[1]));
}

// ---------------- Chebyshev matrix precompute ------------------------------
__global__ void tmat_copy(const float* __restrict__ lap) {
    int i = blockIdx.x * blockDim.x + threadIdx.x;
    if (i < VDIM * VDIM) g_Tm[i] = lap[i];
}
__global__ void tmat_step(const float* __restrict__ lap, int kdst) {
    __shared__ float lrow[VDIM];
    int u = blockIdx.x, v = threadIdx.x;
    if (v < VDIM) lrow[v] = lap[u * VDIM + v];
    __syncthreads();
    if (v >= VDIM) return;
    const float* P = g_Tm + (kdst - 1) * VDIM * VDIM;
    float acc = 0.f;
    for (int w = 0; w < VDIM; w++) acc += lrow[w] * P[w * VDIM + v];
    float q = (kdst == 1) ? ((u == v) ? 1.f : 0.f)
                          : g_Tm[(kdst - 2) * VDIM * VDIM + u * VDIM + v];
    g_Tm[kdst * VDIM * VDIM + u * VDIM + v] = 2.f * acc - q;
}
// A[m][k] = T_kc[v][u], m = kc*162+v, k = u; hi/lo bf16 split, zero-padded
__global__ void pack_T_mma() {
    int i = blockIdx.x * blockDim.x + threadIdx.x;
    if (i >= NPAD2 * KPAD2) return;
    int m = i / KPAD2, u = i % KPAD2;
    float val = 0.f;
    if (m < NROWS && u < VDIM) {
        int kc = (m >= 486) ? 3 : (m >= 324) ? 2 : (m >= 162) ? 1 : 0;
        int v = m - kc * VDIM;
        val = g_Tm[kc * VDIM * VDIM + v * VDIM + u];
    }
    __nv_bfloat16 hi = __float2bfloat16(val);
    __nv_bfloat16 lo = __float2bfloat16(val - __bfloat162float(hi));
    g_Thi[i] = hi; g_Tlo[i] = lo;
}

// ---------------- per-layer source split (fp32 -> bf16 hi/lo) --------------
// grid (SDIM/1024, KPAD2, slices), block 256, 4 s-elems per thread
__global__ void src_split(const float* __restrict__ ext, int sel, int useBn) {
    int s = (blockIdx.x * 256 + threadIdx.x) * 4;
    int k = blockIdx.y;
    int slice = blockIdx.z;
    float4 v = make_float4(0.f, 0.f, 0.f, 0.f);
    if (k < VDIM) {
        const float* src = sel_cbuf(sel, ext) + (size_t)slice * VS;
        v = *(const float4*)&src[(size_t)k * SDIM + s];
        if (useBn) {
            int ch = slice & (ODIM - 1);
            float sc = g_scale[ch], sh = g_shift[ch];
            v.x = fmaxf(fmaf(v.x, sc, sh), 0.f);
            v.y = fmaxf(fmaf(v.y, sc, sh), 0.f);
            v.z = fmaxf(fmaf(v.z, sc, sh), 0.f);
            v.w = fmaxf(fmaf(v.w, sc, sh), 0.f);
        }
    }
    float f[4] = {v.x, v.y, v.z, v.w};
    ushort hi[4], lo[4];
#pragma unroll
    for (int j = 0; j < 4; j++) {
        __nv_bfloat16 h = __float2bfloat16(f[j]);
        __nv_bfloat16 l = __float2bfloat16(f[j] - __bfloat162float(h));
        hi[j] = *(ushort*)&h; lo[j] = *(ushort*)&l;
    }
    size_t off = ((size_t)slice * KPAD2 + k) * SDIM + s;
    *(ushort4*)&g_bhi[off] = make_ushort4(hi[0], hi[1], hi[2], hi[3]);
    *(ushort4*)&g_blo[off] = make_ushort4(lo[0], lo[1], lo[2], lo[3]);
}

// ---------------- tensor-core Chebyshev GEMM -------------------------------
// C[n-rows 128, s 128] per block; K = 176 in 11 chunks; 3-term hi/lo split.
__global__ __launch_bounds__(256) void cheb_mma() {
    __shared__ __align__(128) unsigned char smbuf[2][16384];

    const int tid = threadIdx.x, lane = tid & 31, wid = tid >> 5;
    const int warpM = wid & 1, warpN = wid >> 1;       // 2 x 4 warps
    const int mt = blockIdx.x;                          // 0..5
    const int s0 = blockIdx.y * 128;
    const int slice = blockIdx.z;
    const int m0g = mt * 128;

    const __nv_bfloat16* Bh = g_bhi + (size_t)slice * KPAD2 * SDIM;
    const __nv_bfloat16* Bl = g_blo + (size_t)slice * KPAD2 * SDIM;

    // cp.async thread mapping
    const int cam = tid >> 1, cakh = tid & 1;
    const uint32_t caAdst = (uint32_t)(cam * 32 + ((cakh ^ ((cam >> 2) & 1)) << 4));
    const int cbk = tid >> 4, cbnb = tid & 15;
    const uint32_t caBdst = (uint32_t)(cbk * 256 + ((cbnb ^ (cbk & 7)) << 4));

    uint32_t stb[2] = {smem_u32(smbuf[0]), smem_u32(smbuf[1])};

    auto prefetch = [&](int kc) {
        uint32_t st = stb[kc & 1];
        int k0 = kc * 16;
        size_t aoff = (size_t)(m0g + cam) * KPAD2 + k0 + cakh * 8;
        cpa16(st + caAdst,        g_Thi + aoff);
        cpa16(st + 4096 + caAdst, g_Tlo + aoff);
        size_t boff = (size_t)(k0 + cbk) * SDIM + s0 + cbnb * 8;
        cpa16(st + 8192  + caBdst, Bh + boff);
        cpa16(st + 12288 + caBdst, Bl + boff);
        CP_COMMIT();
    };

    // ldmatrix addressing constants
    const int aRow = ((lane >> 3) & 1) * 8 + (lane & 7);
    const int aKh  = lane >> 4;
    const int bK   = ((lane >> 3) & 1) * 8 + (lane & 7);
    const int bNbO = lane >> 4;

    float acc[4][4][4];
#pragma unroll
    for (int i = 0; i < 4; i++)
#pragma unroll
        for (int j = 0; j < 4; j++)
#pragma unroll
            for (int q = 0; q < 4; q++) acc[i][j][q] = 0.f;

    prefetch(0);
    for (int kc = 0; kc < NKC; kc++) {
        if (kc + 1 < NKC) prefetch(kc + 1);
        if (kc + 1 < NKC) { CP_WAIT(1); } else { CP_WAIT(0); }
        __syncthreads();

        uint32_t st = stb[kc & 1];
        uint32_t Ah[4][4], Al[4][4], Bhf[4][2], Blf[4][2];
#pragma unroll
        for (int f = 0; f < 4; f++) {
            int m = warpM * 64 + f * 16 + aRow;
            uint32_t ad = (uint32_t)(m * 32 + ((aKh ^ ((m >> 2) & 1)) << 4));
            ldsm_x4(Ah[f], st + ad);
            ldsm_x4(Al[f], st + 4096 + ad);
        }
#pragma unroll
        for (int p = 0; p < 2; p++) {
            int nb = warpN * 4 + p * 2 + bNbO;
            uint32_t bd = (uint32_t)(bK * 256 + ((nb ^ (bK & 7)) << 4));
            uint32_t r[4];
            ldsm_x4t(r, st + 8192 + bd);
            Bhf[p*2][0] = r[0]; Bhf[p*2][1] = r[1];
            Bhf[p*2+1][0] = r[2]; Bhf[p*2+1][1] = r[3];
            ldsm_x4t(r, st + 12288 + bd);
            Blf[p*2][0] = r[0]; Blf[p*2][1] = r[1];
            Blf[p*2+1][0] = r[2]; Blf[p*2+1][1] = r[3];
        }
#pragma unroll
        for (int mf = 0; mf < 4; mf++)
#pragma unroll
            for (int nf = 0; nf < 4; nf++) {
                mma_bf16(acc[mf][nf], Ah[mf], Bhf[nf]);
                mma_bf16(acc[mf][nf], Ah[mf], Blf[nf]);
                mma_bf16(acc[mf][nf], Al[mf], Bhf[nf]);
            }
        __syncthreads();
    }

    // Epilogue: scatter fp32 rows to t1..t4
    float* tk[4] = {g_t1, g_t2, g_t3, g_t4};
    const size_t sliceOff = (size_t)slice * VS;
#pragma unroll
    for (int mf = 0; mf < 4; mf++) {
        int mbase = m0g + warpM * 64 + mf * 16 + (lane >> 2);
#pragma unroll
        for (int half = 0; half < 2; half++) {
            int n = mbase + half * 8;
            if (n < NROWS) {
                int kc = (n >= 486) ? 3 : (n >= 324) ? 2 : (n >= 162) ? 1 : 0;
                int v = n - kc * VDIM;
                float* dst = tk[kc] + sliceOff + (size_t)v * SDIM
                           + s0 + warpN * 32 + (lane & 3) * 2;
#pragma unroll
                for (int nf = 0; nf < 4; nf++) {
                    float2 val = half ? make_float2(acc[mf][nf][2], acc[mf][nf][3])
                                      : make_float2(acc[mf][nf][0], acc[mf][nf][1]);
                    *(float2*)(dst + nf * 8) = val;
                }
            }
        }
    }
}

// ---------------- combine (FFMA2 o-pairs) + fused BN stats -----------------
__global__ __launch_bounds__(128) void combine(
    const float* __restrict__ x0ext, int x0Sel, int Fin, int useBn,
    const float* __restrict__ w, const float* __restrict__ bias)
{
    const int KF = KCH * Fin;
    __shared__ __align__(16) float Ws[KCH * F2][32];
    __shared__ float Ts[16][256];
    __shared__ const float* rows[KCH * F2];
    __shared__ float s_sum[ODIM], s_sq[ODIM];
    __shared__ float s_sc[F2], s_sh[F2];

    const int tid = threadIdx.x;
    const int b   = blockIdx.y;
    const size_t n0 = (size_t)blockIdx.x * 256;

    const float* x0 = sel_cbuf(x0Sel, x0ext);
    const float* bufs[KCH] = {x0, g_t1, g_t2, g_t3, g_t4};

    for (int i = tid; i < KF; i += 128) {
        int k = i / Fin, f = i % Fin;
        rows[i] = bufs[k] + ((size_t)(b * Fin + f)) * VS;
    }
    for (int i = tid; i < KF * 32; i += 128) Ws[0][i] = w[i];
    if (tid < ODIM) { s_sum[tid] = 0.f; s_sq[tid] = 0.f; }
    if (tid < Fin) {
        s_sc[tid] = useBn ? g_scale[tid] : 1.f;
        s_sh[tid] = useBn ? g_shift[tid] : 0.f;
    }
    __syncthreads();

    const int to = tid & 3;    // o dir (4)
    const int tn = tid >> 2;   // n dir (32)

    ULL acc2[4][8];
#pragma unroll
    for (int p = 0; p < 4; p++)
#pragma unroll
        for (int j = 0; j < 8; j++) acc2[p][j] = 0ull;

    for (int kc0 = 0; kc0 < KF; kc0 += 16) {
        for (int i = tid; i < 16 * 64; i += 128) {
            int kk = i >> 6, jq = i & 63;
            int kr = kc0 + kk;
            float4 v = *(const float4*)&rows[kr][n0 + jq * 4];
            if (useBn && kr < Fin) {
                float a = s_sc[kr], c = s_sh[kr];
                v.x = fmaxf(fmaf(v.x, a, c), 0.f);
                v.y = fmaxf(fmaf(v.y, a, c), 0.f);
                v.z = fmaxf(fmaf(v.z, a, c), 0.f);
                v.w = fmaxf(fmaf(v.w, a, c), 0.f);
            }
            *(float4*)&Ts[kk][jq * 4] = v;
        }
        __syncthreads();
#pragma unroll 2
        for (int kk = 0; kk < 16; kk++) {
            const ULL* wp = (const ULL*)&Ws[kc0 + kk][0];
            ULL ap[4] = {wp[to * 2], wp[to * 2 + 1], wp[8 + to * 2], wp[9 + to * 2]};
            float bb[8];
            *(float4*)&bb[0] = *(const float4*)&Ts[kk][tn * 4];
            *(float4*)&bb[4] = *(const float4*)&Ts[kk][128 + tn * 4];
            ULL bd[8];
#pragma unroll
            for (int j = 0; j < 8; j++) bd[j] = f2dup(bb[j]);
#pragma unroll
            for (int p = 0; p < 4; p++)
#pragma unroll
                for (int j = 0; j < 8; j++)
                    acc2[p][j] = ffma2(ap[p], bd[j], acc2[p][j]);
        }
        __syncthreads();
    }

    const int obase[4] = {to * 4, to * 4 + 2, 16 + to * 4, 16 + to * 4 + 2};
#pragma unroll
    for (int p = 0; p < 4; p++) {
        float cl[8], ch[8];
#pragma unroll
        for (int j = 0; j < 8; j++) f2unpack(acc2[p][j], cl[j], ch[j]);
        float* crow[2] = {cl, ch};
#pragma unroll
        for (int q = 0; q < 2; q++) {
            int o = obase[p] + q;
            float bo = bias[o];
            float* c = crow[q];
            float* yo = g_y + ((size_t)(b * ODIM + o)) * VS + n0;
            float4 v0 = make_float4(c[0] + bo, c[1] + bo, c[2] + bo, c[3] + bo);
            float4 v1 = make_float4(c[4] + bo, c[5] + bo, c[6] + bo, c[7] + bo);
            *(float4*)&yo[tn * 4]       = v0;
            *(float4*)&yo[128 + tn * 4] = v1;
            float ps = v0.x + v0.y + v0.z + v0.w + v1.x + v1.y + v1.z + v1.w;
            float pq = v0.x*v0.x + v0.y*v0.y + v0.z*v0.z + v0.w*v0.w
                     + v1.x*v1.x + v1.y*v1.y + v1.z*v1.z + v1.w*v1.w;
            atomicAdd(&s_sum[o], ps);
            atomicAdd(&s_sq[o],  pq);
        }
    }
    __syncthreads();
    if (tid < ODIM) {
        atomicAdd(&g_sum[tid],   s_sum[tid]);
        atomicAdd(&g_sumsq[tid], s_sq[tid]);
    }
}

__global__ void zero_stats() {
    int i = threadIdx.x;
    if (i < ODIM) { g_sum[i] = 0.f; g_sumsq[i] = 0.f; }
}

__global__ void finalize_stats(const float* __restrict__ gamma,
                               const float* __restrict__ beta, float ncnt)
{
    int o = threadIdx.x;
    if (o < ODIM) {
        float mean = g_sum[o] / ncnt;
        float var  = g_sumsq[o] / ncnt - mean * mean;
        float sc   = gamma[o] * rsqrtf(var + 1e-5f);
        g_scale[o] = sc;
        g_shift[o] = beta[o] - mean * sc;
    }
}

__global__ void norm_relu(float* __restrict__ out)
{
    const size_t total4 = MAXELEM / 4;
    const size_t stride = (size_t)gridDim.x * blockDim.x;
    for (size_t i = (size_t)blockIdx.x * blockDim.x + threadIdx.x;
         i < total4; i += stride) {
        size_t e = i * 4;
        int o = (int)((e / VS) % ODIM);
        float sc = g_scale[o], sh = g_shift[o];
        float4 v = ((const float4*)g_y)[i];
        v.x = fmaxf(fmaf(v.x, sc, sh), 0.f);
        v.y = fmaxf(fmaf(v.y, sc, sh), 0.f);
        v.z = fmaxf(fmaf(v.z, sc, sh), 0.f);
        v.w = fmaxf(fmaf(v.w, sc, sh), 0.f);
        ((float4*)out)[i] = v;
    }
}

// ---------------------------------------------------------------------------
extern "C" void kernel_launch(void* const* d_in, const int* in_sizes, int n_in,
                              void* d_out, int out_size)
{
    const float* x   = (const float*)d_in[0];
    const float* lap = (const float*)d_in[1];
    const float* w1  = (const float*)d_in[2];
    const float* b1  = (const float*)d_in[3];
    const float* g1  = (const float*)d_in[4];
    const float* be1 = (const float*)d_in[5];
    const float* w2  = (const float*)d_in[6];
    const float* b2  = (const float*)d_in[7];
    const float* g2  = (const float*)d_in[8];
    const float* be2 = (const float*)d_in[9];
    float* out = (float*)d_out;
    (void)in_sizes; (void)n_in; (void)out_size;

    const float ncnt = (float)((size_t)BDIM * VS);
    dim3 gcomb(VS / 256, BDIM);

    // Precompute T1..T4 and bf16 hi/lo A operand
    tmat_copy<<<(VDIM * VDIM + 255) / 256, 256>>>(lap);
    tmat_step<<<VDIM, 192>>>(lap, 1);
    tmat_step<<<VDIM, 192>>>(lap, 2);
    tmat_step<<<VDIM, 192>>>(lap, 3);
    pack_T_mma<<<(NPAD2 * KPAD2 + 255) / 256, 256>>>();

    // ---- Layer 1 ----
    src_split<<<dim3(SDIM / 1024, KPAD2, BDIM * F1), 256>>>(x, 5, 0);
    cheb_mma<<<dim3(6, SDIM / 128, BDIM * F1), 256>>>();
    zero_stats<<<1, 32>>>();
    combine<<<gcomb, 128>>>(x, 5, F1, 0, w1, b1);
    finalize_stats<<<1, 32>>>(g1, be1, ncnt);

    // ---- Layer 2 ----
    src_split<<<dim3(SDIM / 1024, KPAD2, BDIM * F2), 256>>>(nullptr, 6, 1);
    cheb_mma<<<dim3(6, SDIM / 128, BDIM * F2), 256>>>();
    zero_stats<<<1, 32>>>();
    combine<<<gcomb, 128>>>(nullptr, 6, F2, 1, w2, b2);
    finalize_stats<<<1, 32>>>(g2, be2, ncnt);
    norm_relu<<<2048, 256>>>(out);
}

// round 6
// speedup vs baseline: 2.6240x; 1.2842x over previous
#include <cuda_runtime.h>
#include <cuda_bf16.h>
#include <math.h>
#include <stdint.h>

// Problem constants
#define BDIM   2
#define VDIM   162
#define SDIM   4096
#define VS     (VDIM * SDIM)        // 663552
#define ODIM   32
#define KCH    5
#define F1     16
#define F2     32
#define NROWS  648                  // 4 * 162 stacked (k, v) rows
#define NPAD2  768                  // 6 m-tiles of 128
#define KPAD2  176                  // 11 k-chunks of 16
#define NKC    11
#define KFMAX  160
#define MAXELEM ((size_t)BDIM * ODIM * VS)

typedef unsigned long long ULL;
typedef unsigned short u16;

// Scratch
__device__ float g_y [BDIM * ODIM * VS];                       // 170 MB
__device__ float g_sum[ODIM];
__device__ float g_sumsq[ODIM];
__device__ float g_scale[ODIM];
__device__ float g_shift[ODIM];
__device__ float g_Tm[4 * VDIM * VDIM];                        // T1..T4 [v][u]
__device__ __align__(16) __nv_bfloat16 g_Thi[NPAD2 * KPAD2];   // A hi [m][k]
__device__ __align__(16) __nv_bfloat16 g_Tlo[NPAD2 * KPAD2];
__device__ __align__(16) __nv_bfloat16 g_bhi[(size_t)BDIM * F2 * KPAD2 * SDIM]; // 184MB
__device__ __align__(16) __nv_bfloat16 g_blo[(size_t)BDIM * F2 * KPAD2 * SDIM];
__device__ __align__(16) __nv_bfloat16 g_thi[(size_t)BDIM * F2 * NROWS * SDIM]; // 340MB
__device__ __align__(16) __nv_bfloat16 g_tlo[(size_t)BDIM * F2 * NROWS * SDIM];

// ---------------- helpers ---------------------------------------------------
__device__ __forceinline__ uint32_t smem_u32(const void* p) {
    uint32_t a;
    asm("{ .reg .u64 t; cvta.to.shared.u64 t, %1; cvt.u32.u64 %0, t; }" : "=r"(a) : "l"(p));
    return a;
}
__device__ __forceinline__ void cpa16(uint32_t s, const void* g) {
    asm volatile("cp.async.cg.shared.global [%0], [%1], 16;" :: "r"(s), "l"(g));
}
#define CP_COMMIT() asm volatile("cp.async.commit_group;" ::: "memory")
#define CP_WAIT(n)  asm volatile("cp.async.wait_group %0;" :: "n"(n) : "memory")

__device__ __forceinline__ void ldsm_x4(uint32_t* r, uint32_t a) {
    asm volatile("ldmatrix.sync.aligned.m8n8.x4.shared.b16 {%0,%1,%2,%3}, [%4];"
        : "=r"(r[0]), "=r"(r[1]), "=r"(r[2]), "=r"(r[3]) : "r"(a));
}
__device__ __forceinline__ void ldsm_x4t(uint32_t* r, uint32_t a) {
    asm volatile("ldmatrix.sync.aligned.m8n8.x4.trans.shared.b16 {%0,%1,%2,%3}, [%4];"
        : "=r"(r[0]), "=r"(r[1]), "=r"(r[2]), "=r"(r[3]) : "r"(a));
}
__device__ __forceinline__ void mma_bf16(float* c, const uint32_t* a, const uint32_t* b) {
    asm volatile("mma.sync.aligned.m16n8k16.row.col.f32.bf16.bf16.f32 "
        "{%0,%1,%2,%3}, {%4,%5,%6,%7}, {%8,%9}, {%0,%1,%2,%3};"
        : "+f"(c[0]), "+f"(c[1]), "+f"(c[2]), "+f"(c[3])
        : "r"(a[0]), "r"(a[1]), "r"(a[2]), "r"(a[3]), "r"(b[0]), "r"(b[1]));
}
__device__ __forceinline__ u16 bfu(__nv_bfloat16 h) { return *(u16*)&h; }

// ---------------- Chebyshev matrix precompute ------------------------------
__global__ void tmat_copy(const float* __restrict__ lap) {
    int i = blockIdx.x * blockDim.x + threadIdx.x;
    if (i < VDIM * VDIM) g_Tm[i] = lap[i];
}
__global__ void tmat_step(const float* __restrict__ lap, int kdst) {
    __shared__ float lrow[VDIM];
    int u = blockIdx.x, v = threadIdx.x;
    if (v < VDIM) lrow[v] = lap[u * VDIM + v];
    __syncthreads();
    if (v >= VDIM) return;
    const float* P = g_Tm + (kdst - 1) * VDIM * VDIM;
    float acc = 0.f;
    for (int w = 0; w < VDIM; w++) acc += lrow[w] * P[w * VDIM + v];
    float q = (kdst == 1) ? ((u == v) ? 1.f : 0.f)
                          : g_Tm[(kdst - 2) * VDIM * VDIM + u * VDIM + v];
    g_Tm[kdst * VDIM * VDIM + u * VDIM + v] = 2.f * acc - q;
}
__global__ void pack_T_mma() {
    int i = blockIdx.x * blockDim.x + threadIdx.x;
    if (i >= NPAD2 * KPAD2) return;
    int m = i / KPAD2, u = i % KPAD2;
    float val = 0.f;
    if (m < NROWS && u < VDIM) {
        int kc = (m >= 486) ? 3 : (m >= 324) ? 2 : (m >= 162) ? 1 : 0;
        int v = m - kc * VDIM;
        val = g_Tm[kc * VDIM * VDIM + v * VDIM + u];
    }
    __nv_bfloat16 hi = __float2bfloat16(val);
    __nv_bfloat16 lo = __float2bfloat16(val - __bfloat162float(hi));
    g_Thi[i] = hi; g_Tlo[i] = lo;
}

// ---------------- per-layer source split (fp32 -> bf16 hi/lo) --------------
__global__ void src_split(const float* __restrict__ ext, int useY, int useBn) {
    int s = (blockIdx.x * 256 + threadIdx.x) * 4;
    int k = blockIdx.y;
    int slice = blockIdx.z;
    float4 v = make_float4(0.f, 0.f, 0.f, 0.f);
    if (k < VDIM) {
        const float* src = (useY ? g_y : ext) + (size_t)slice * VS;
        v = *(const float4*)&src[(size_t)k * SDIM + s];
        if (useBn) {
            int ch = slice & (ODIM - 1);
            float sc = g_scale[ch], sh = g_shift[ch];
            v.x = fmaxf(fmaf(v.x, sc, sh), 0.f);
            v.y = fmaxf(fmaf(v.y, sc, sh), 0.f);
            v.z = fmaxf(fmaf(v.z, sc, sh), 0.f);
            v.w = fmaxf(fmaf(v.w, sc, sh), 0.f);
        }
    }
    float f[4] = {v.x, v.y, v.z, v.w};
    u16 hi[4], lo[4];
#pragma unroll
    for (int j = 0; j < 4; j++) {
        __nv_bfloat16 h = __float2bfloat16(f[j]);
        __nv_bfloat16 l = __float2bfloat16(f[j] - __bfloat162float(h));
        hi[j] = bfu(h); lo[j] = bfu(l);
    }
    size_t off = ((size_t)slice * KPAD2 + k) * SDIM + s;
    *(ushort4*)&g_bhi[off] = make_ushort4(hi[0], hi[1], hi[2], hi[3]);
    *(ushort4*)&g_blo[off] = make_ushort4(lo[0], lo[1], lo[2], lo[3]);
}

// ---------------- tensor-core Chebyshev GEMM -------------------------------
__global__ __launch_bounds__(256) void cheb_mma() {
    __shared__ __align__(128) unsigned char smbuf[2][16384];

    const int tid = threadIdx.x, lane = tid & 31, wid = tid >> 5;
    const int warpM = wid & 1, warpN = wid >> 1;
    const int mt = blockIdx.x;
    const int s0 = blockIdx.y * 128;
    const int slice = blockIdx.z;
    const int m0g = mt * 128;

    const __nv_bfloat16* Bh = g_bhi + (size_t)slice * KPAD2 * SDIM;
    const __nv_bfloat16* Bl = g_blo + (size_t)slice * KPAD2 * SDIM;

    const int cam = tid >> 1, cakh = tid & 1;
    const uint32_t caAdst = (uint32_t)(cam * 32 + ((cakh ^ ((cam >> 2) & 1)) << 4));
    const int cbk = tid >> 4, cbnb = tid & 15;
    const uint32_t caBdst = (uint32_t)(cbk * 256 + ((cbnb ^ (cbk & 7)) << 4));

    uint32_t stb[2] = {smem_u32(smbuf[0]), smem_u32(smbuf[1])};

    auto prefetch = [&](int kc) {
        uint32_t st = stb[kc & 1];
        int k0 = kc * 16;
        size_t aoff = (size_t)(m0g + cam) * KPAD2 + k0 + cakh * 8;
        cpa16(st + caAdst,        g_Thi + aoff);
        cpa16(st + 4096 + caAdst, g_Tlo + aoff);
        size_t boff = (size_t)(k0 + cbk) * SDIM + s0 + cbnb * 8;
        cpa16(st + 8192  + caBdst, Bh + boff);
        cpa16(st + 12288 + caBdst, Bl + boff);
        CP_COMMIT();
    };

    const int aRow = ((lane >> 3) & 1) * 8 + (lane & 7);
    const int aKh  = lane >> 4;
    const int bK   = ((lane >> 3) & 1) * 8 + (lane & 7);
    const int bNbO = lane >> 4;

    float acc[4][4][4];
#pragma unroll
    for (int i = 0; i < 4; i++)
#pragma unroll
        for (int j = 0; j < 4; j++)
#pragma unroll
            for (int q = 0; q < 4; q++) acc[i][j][q] = 0.f;

    prefetch(0);
    for (int kc = 0; kc < NKC; kc++) {
        if (kc + 1 < NKC) { prefetch(kc + 1); CP_WAIT(1); } else { CP_WAIT(0); }
        __syncthreads();

        uint32_t st = stb[kc & 1];
        uint32_t Ah[4][4], Al[4][4], Bhf[4][2], Blf[4][2];
#pragma unroll
        for (int f = 0; f < 4; f++) {
            int m = warpM * 64 + f * 16 + aRow;
            uint32_t ad = (uint32_t)(m * 32 + ((aKh ^ ((m >> 2) & 1)) << 4));
            ldsm_x4(Ah[f], st + ad);
            ldsm_x4(Al[f], st + 4096 + ad);
        }
#pragma unroll
        for (int p = 0; p < 2; p++) {
            int nb = warpN * 4 + p * 2 + bNbO;
            uint32_t bd = (uint32_t)(bK * 256 + ((nb ^ (bK & 7)) << 4));
            uint32_t r[4];
            ldsm_x4t(r, st + 8192 + bd);
            Bhf[p*2][0] = r[0]; Bhf[p*2][1] = r[1];
            Bhf[p*2+1][0] = r[2]; Bhf[p*2+1][1] = r[3];
            ldsm_x4t(r, st + 12288 + bd);
            Blf[p*2][0] = r[0]; Blf[p*2][1] = r[1];
            Blf[p*2+1][0] = r[2]; Blf[p*2+1][1] = r[3];
        }
#pragma unroll
        for (int mf = 0; mf < 4; mf++)
#pragma unroll
            for (int nf = 0; nf < 4; nf++) {
                mma_bf16(acc[mf][nf], Ah[mf], Bhf[nf]);
                mma_bf16(acc[mf][nf], Ah[mf], Blf[nf]);
                mma_bf16(acc[mf][nf], Al[mf], Bhf[nf]);
            }
        __syncthreads();
    }

    // Epilogue: write t rows as bf16 hi/lo; layout [slice][n 0..647][s]
    const size_t sliceBase = (size_t)slice * NROWS * SDIM;
#pragma unroll
    for (int mf = 0; mf < 4; mf++) {
        int mbase = m0g + warpM * 64 + mf * 16 + (lane >> 2);
#pragma unroll
        for (int half = 0; half < 2; half++) {
            int n = mbase + half * 8;
            if (n < NROWS) {
                size_t off = sliceBase + (size_t)n * SDIM
                           + s0 + warpN * 32 + (lane & 3) * 2;
#pragma unroll
                for (int nf = 0; nf < 4; nf++) {
                    float2 val = half ? make_float2(acc[mf][nf][2], acc[mf][nf][3])
                                      : make_float2(acc[mf][nf][0], acc[mf][nf][1]);
                    __nv_bfloat16 h0 = __float2bfloat16(val.x);
                    __nv_bfloat16 h1 = __float2bfloat16(val.y);
                    __nv_bfloat16 l0 = __float2bfloat16(val.x - __bfloat162float(h0));
                    __nv_bfloat16 l1 = __float2bfloat16(val.y - __bfloat162float(h1));
                    *(ushort2*)&g_thi[off + nf * 8] = make_ushort2(bfu(h0), bfu(h1));
                    *(ushort2*)&g_tlo[off + nf * 8] = make_ushort2(bfu(l0), bfu(l1));
                }
            }
        }
    }
}

// ---------------- combine via mma.sync (M=32, K=KF, N=128/block) -----------
// y[b,o,(v,s)] = bias[o] + sum_{kf} w[kf,o] * trow_kf[(v,s)]
__global__ __launch_bounds__(256) void combine_mma(
    const float* __restrict__ w, const float* __restrict__ bias, int Fin)
{
    __shared__ ULL pHi[KFMAX], pLo[KFMAX];
    __shared__ __align__(16) u16 Ahw[10 * 512];     // [chunk][o][16k], swizzled
    __shared__ __align__(16) u16 Alw[10 * 512];
    __shared__ __align__(128) u16 Bb[2][2][2048];   // [buf][split][16k x 128s]
    __shared__ float s_sum[ODIM], s_sq[ODIM];

    const int tid = threadIdx.x, lane = tid & 31, wid = tid >> 5;
    const int warpM = wid & 1, warpN = wid >> 1;    // 2 x 4
    const int KF = KCH * Fin, NKCc = KF / 16;
    const int n0 = blockIdx.x * 128;
    const int v = n0 >> 12, sOff = n0 & 4095;
    const int b = blockIdx.y;

    // row pointer table
    for (int i = tid; i < KF; i += 256) {
        int k = i / Fin, f = i % Fin, slice = b * Fin + f;
        if (k == 0) {
            size_t o = ((size_t)slice * KPAD2 + v) * SDIM + sOff;
            pHi[i] = (ULL)(g_bhi + o); pLo[i] = (ULL)(g_blo + o);
        } else {
            size_t o = ((size_t)slice * NROWS + (size_t)(k - 1) * VDIM + v) * SDIM + sOff;
            pHi[i] = (ULL)(g_thi + o); pLo[i] = (ULL)(g_tlo + o);
        }
    }
    // W -> A smem (hi/lo split, ldmatrix-swizzled)
    for (int i = tid; i < KF * 32; i += 256) {
        int kf = i >> 5, o = i & 31;
        float val = w[i];
        __nv_bfloat16 h = __float2bfloat16(val);
        __nv_bfloat16 l = __float2bfloat16(val - __bfloat162float(h));
        int c = kf >> 4, kw = kf & 15, kh = kw >> 3, kb = kw & 7;
        int addr = c * 512 + o * 16 + ((kh ^ ((o >> 2) & 1)) << 3) + kb;
        Ahw[addr] = bfu(h); Alw[addr] = bfu(l);
    }
    if (tid < ODIM) { s_sum[tid] = 0.f; s_sq[tid] = 0.f; }
    __syncthreads();

    const uint32_t aHib = smem_u32(Ahw), aLob = smem_u32(Alw);
    const uint32_t bB[2][2] = {
        {smem_u32(Bb[0][0]), smem_u32(Bb[0][1])},
        {smem_u32(Bb[1][0]), smem_u32(Bb[1][1])}
    };

    const int row = tid >> 4, seg = tid & 15;
    const uint32_t bdst = (uint32_t)(row * 256 + ((seg ^ (row & 7)) << 4));

    auto prefetch = [&](int c) {
        int kf = c * 16 + row;
        cpa16(bB[c & 1][0] + bdst, (const u16*)pHi[kf] + seg * 8);
        cpa16(bB[c & 1][1] + bdst, (const u16*)pLo[kf] + seg * 8);
        CP_COMMIT();
    };

    const int aRow = ((lane >> 3) & 1) * 8 + (lane & 7);
    const int aKh  = lane >> 4;
    const int bK   = ((lane >> 3) & 1) * 8 + (lane & 7);
    const int bNbO = lane >> 4;

    float acc[4][4];
#pragma unroll
    for (int i = 0; i < 4; i++)
#pragma unroll
        for (int q = 0; q < 4; q++) acc[i][q] = 0.f;

    prefetch(0);
    for (int c = 0; c < NKCc; c++) {
        if (c + 1 < NKCc) { prefetch(c + 1); CP_WAIT(1); } else { CP_WAIT(0); }
        __syncthreads();

        int ar = warpM * 16 + aRow;
        uint32_t aad = (uint32_t)(c * 1024 + ar * 32 + ((aKh ^ ((ar >> 2) & 1)) << 4));
        uint32_t Af[4], Alf_[4];
        ldsm_x4(Af,  aHib + aad);
        ldsm_x4(Alf_, aLob + aad);

        uint32_t Bhf[4][2], Blf[4][2];
#pragma unroll
        for (int p = 0; p < 2; p++) {
            int nb = warpN * 4 + p * 2 + bNbO;
            uint32_t bd = (uint32_t)(bK * 256 + ((nb ^ (bK & 7)) << 4));
            uint32_t r[4];
            ldsm_x4t(r, bB[c & 1][0] + bd);
            Bhf[p*2][0] = r[0]; Bhf[p*2][1] = r[1];
            Bhf[p*2+1][0] = r[2]; Bhf[p*2+1][1] = r[3];
            ldsm_x4t(r, bB[c & 1][1] + bd);
            Blf[p*2][0] = r[0]; Blf[p*2][1] = r[1];
            Blf[p*2+1][0] = r[2]; Blf[p*2+1][1] = r[3];
        }
#pragma unroll
        for (int nf = 0; nf < 4; nf++) {
            mma_bf16(acc[nf], Af,   Bhf[nf]);
            mma_bf16(acc[nf], Af,   Blf[nf]);
            mma_bf16(acc[nf], Alf_, Bhf[nf]);
        }
        __syncthreads();
    }

    // Epilogue: y = acc + bias, fused BN stats
    const int orow = warpM * 16 + (lane >> 2);
#pragma unroll
    for (int half = 0; half < 2; half++) {
        int o = orow + half * 8;
        float bo = bias[o];
        float* yo = g_y + ((size_t)(b * ODIM + o)) * VS + n0 + warpN * 32 + (lane & 3) * 2;
        float ps = 0.f, pq = 0.f;
#pragma unroll
        for (int nf = 0; nf < 4; nf++) {
            float2 val = half ? make_float2(acc[nf][2], acc[nf][3])
                              : make_float2(acc[nf][0], acc[nf][1]);
            val.x += bo; val.y += bo;
            *(float2*)(yo + nf * 8) = val;
            ps += val.x + val.y;
            pq += val.x * val.x + val.y * val.y;
        }
        atomicAdd(&s_sum[o], ps);
        atomicAdd(&s_sq[o],  pq);
    }
    __syncthreads();
    if (tid < ODIM) {
        atomicAdd(&g_sum[tid],   s_sum[tid]);
        atomicAdd(&g_sumsq[tid], s_sq[tid]);
    }
}

__global__ void zero_stats() {
    int i = threadIdx.x;
    if (i < ODIM) { g_sum[i] = 0.f; g_sumsq[i] = 0.f; }
}

__global__ void finalize_stats(const float* __restrict__ gamma,
                               const float* __restrict__ beta, float ncnt)
{
    int o = threadIdx.x;
    if (o < ODIM) {
        float mean = g_sum[o] / ncnt;
        float var  = g_sumsq[o] / ncnt - mean * mean;
        float sc   = gamma[o] * rsqrtf(var + 1e-5f);
        g_scale[o] = sc;
        g_shift[o] = beta[o] - mean * sc;
    }
}

__global__ void norm_relu(float* __restrict__ out)
{
    const size_t total4 = MAXELEM / 4;
    const size_t stride = (size_t)gridDim.x * blockDim.x;
    for (size_t i = (size_t)blockIdx.x * blockDim.x + threadIdx.x;
         i < total4; i += stride) {
        size_t e = i * 4;
        int o = (int)((e / VS) % ODIM);
        float sc = g_scale[o], sh = g_shift[o];
        float4 v = ((const float4*)g_y)[i];
        v.x = fmaxf(fmaf(v.x, sc, sh), 0.f);
        v.y = fmaxf(fmaf(v.y, sc, sh), 0.f);
        v.z = fmaxf(fmaf(v.z, sc, sh), 0.f);
        v.w = fmaxf(fmaf(v.w, sc, sh), 0.f);
        ((float4*)out)[i] = v;
    }
}

// ---------------------------------------------------------------------------
extern "C" void kernel_launch(void* const* d_in, const int* in_sizes, int n_in,
                              void* d_out, int out_size)
{
    const float* x   = (const float*)d_in[0];
    const float* lap = (const float*)d_in[1];
    const float* w1  = (const float*)d_in[2];
    const float* b1  = (const float*)d_in[3];
    const float* g1  = (const float*)d_in[4];
    const float* be1 = (const float*)d_in[5];
    const float* w2  = (const float*)d_in[6];
    const float* b2  = (const float*)d_in[7];
    const float* g2  = (const float*)d_in[8];
    const float* be2 = (const float*)d_in[9];
    float* out = (float*)d_out;
    (void)in_sizes; (void)n_in; (void)out_size;

    const float ncnt = (float)((size_t)BDIM * VS);
    dim3 gcomb(VS / 128, BDIM);

    tmat_copy<<<(VDIM * VDIM + 255) / 256, 256>>>(lap);
    tmat_step<<<VDIM, 192>>>(lap, 1);
    tmat_step<<<VDIM, 192>>>(lap, 2);
    tmat_step<<<VDIM, 192>>>(lap, 3);
    pack_T_mma<<<(NPAD2 * KPAD2 + 255) / 256, 256>>>();

    // ---- Layer 1 ----
    src_split<<<dim3(SDIM / 1024, KPAD2, BDIM * F1), 256>>>(x, 0, 0);
    cheb_mma<<<dim3(6, SDIM / 128, BDIM * F1), 256>>>();
    zero_stats<<<1, 32>>>();
    combine_mma<<<gcomb, 256>>>(w1, b1, F1);
    finalize_stats<<<1, 32>>>(g1, be1, ncnt);

    // ---- Layer 2 ----
    src_split<<<dim3(SDIM / 1024, KPAD2, BDIM * F2), 256>>>(nullptr, 1, 1);
    cheb_mma<<<dim3(6, SDIM / 128, BDIM * F2), 256>>>();
    zero_stats<<<1, 32>>>();
    combine_mma<<<gcomb, 256>>>(w2, b2, F2);
    finalize_stats<<<1, 32>>>(g2, be2, ncnt);
    norm_relu<<<2048, 256>>>(out);
}